// round 16
// baseline (speedup 1.0000x reference)
#include <cuda_runtime.h>
#include <cstdint>

// Problem constants
#define B_   4
#define S_   1024
#define D_   1024
#define H_   16
#define HD_  64
#define QKVN 3072
#define M_   (B_ * S_)

// Scratch (static device globals — allocation-free per harness rules)
__device__ float g_qkv[(size_t)M_ * QKVN];     // [b,s, h*192 + {q,k,v}*64]
__device__ float g_ctx[(size_t)M_ * D_];       // [b,s, h*64+d]
__device__ float2 g_part[(size_t)B_ * H_ * S_ * 16];  // per (bh,q,chunk64): (max, expsum)
__device__ float g_wt[(size_t)QKVN * D_];      // Wqkv^T : [n][k]
__device__ float g_wot[(size_t)D_ * D_];       // Wo^T   : [n][k]

// ---------------------------------------------------------------------------
// helpers
// ---------------------------------------------------------------------------
__device__ __forceinline__ float to_tf32(float x) {
    uint32_t u;
    asm("cvt.rna.tf32.f32 %0, %1;" : "=r"(u) : "f"(x));
    return __uint_as_float(u);
}

__device__ __forceinline__ void mma_tf32(float* d, const uint32_t* a, const uint32_t* b) {
    asm volatile(
        "mma.sync.aligned.m16n8k8.row.col.f32.tf32.tf32.f32 "
        "{%0,%1,%2,%3}, {%4,%5,%6,%7}, {%8,%9}, {%0,%1,%2,%3};\n"
        : "+f"(d[0]), "+f"(d[1]), "+f"(d[2]), "+f"(d[3])
        : "r"(a[0]), "r"(a[1]), "r"(a[2]), "r"(a[3]), "r"(b[0]), "r"(b[1]));
}

__device__ __forceinline__ void ldsm_x4(uint32_t& r0, uint32_t& r1,
                                        uint32_t& r2, uint32_t& r3, uint32_t addr) {
    asm volatile("ldmatrix.sync.aligned.m8n8.x4.shared.b16 {%0,%1,%2,%3}, [%4];"
                 : "=r"(r0), "=r"(r1), "=r"(r2), "=r"(r3) : "r"(addr));
}

// ---------------------------------------------------------------------------
// transpose: Wt[n][k] = W[k][n]  (W is [K][N] row-major); dst selected by flag
// ---------------------------------------------------------------------------
__global__ __launch_bounds__(256) void transpose_kernel(
    const float* __restrict__ W, int N, int K, int dst_sel)
{
    float* Wt = dst_sel ? g_wot : g_wt;
    __shared__ float t[32][33];
    const int n0 = blockIdx.x * 32, k0 = blockIdx.y * 32;
    const int tx = threadIdx.x & 31, ty = threadIdx.x >> 5;  // 32 x 8
#pragma unroll
    for (int i = 0; i < 4; i++)
        t[ty + 8 * i][tx] = W[(size_t)(k0 + ty + 8 * i) * N + n0 + tx];
    __syncthreads();
#pragma unroll
    for (int i = 0; i < 4; i++)
        Wt[(size_t)(n0 + ty + 8 * i) * K + k0 + tx] = t[tx][ty + 8 * i];
}

// ---------------------------------------------------------------------------
// tf32 GEMM with ldmatrix fragment feeds (FROZEN from R14).
// ---------------------------------------------------------------------------
#define BK   32
#define TSTR 36

__device__ __forceinline__ void gemm_lds_body(
    const float* __restrict__ A, const float* __restrict__ Bt,
    const float* __restrict__ bias, float* __restrict__ C,
    int N, int K)
{
    __shared__ float As[128 * TSTR];
    __shared__ float Bs[128 * TSTR];

    const int tid  = threadIdx.x;
    const int lane = tid & 31;
    const int wid  = tid >> 5;
    const int wm   = (wid & 3) * 32;
    const int wn   = (wid >> 2) * 64;
    const int bx   = blockIdx.x * 128;
    const int by   = blockIdx.y * 128;

    const int g = lane >> 2;
    const int a = lane & 3;

    float acc[2][8][4];
#pragma unroll
    for (int i = 0; i < 2; i++)
#pragma unroll
        for (int j = 0; j < 8; j++)
#pragma unroll
            for (int v = 0; v < 4; v++) acc[i][j][v] = 0.f;

    const int srow = tid >> 3;
    const int scol = (tid & 7) * 4;

    const uint32_t as_base = (uint32_t)__cvta_generic_to_shared(As);
    const uint32_t bs_base = (uint32_t)__cvta_generic_to_shared(Bs);
    uint32_t aoff[2], boff[4];
#pragma unroll
    for (int i = 0; i < 2; i++)
        aoff[i] = as_base +
            ((wm + i * 16 + ((lane >> 3) & 1) * 8 + (lane & 7)) * TSTR
             + (lane >> 4) * 4) * 4;
#pragma unroll
    for (int jj = 0; jj < 4; jj++)
        boff[jj] = bs_base +
            ((wn + 8 * (2 * jj + (lane >> 4)) + (lane & 7)) * TSTR
             + ((lane >> 3) & 1) * 4) * 4;

    for (int k0 = 0; k0 < K; k0 += BK) {
        float4 av[4], bv[4];
#pragma unroll
        for (int i = 0; i < 4; i++)
            av[i] = *(const float4*)(A + (size_t)(by + srow + 32 * i) * K + k0 + scol);
#pragma unroll
        for (int i = 0; i < 4; i++)
            bv[i] = *(const float4*)(Bt + (size_t)(bx + srow + 32 * i) * K + k0 + scol);

        __syncthreads();
#pragma unroll
        for (int i = 0; i < 4; i++) {
            float4 t = av[i];
            t.x = to_tf32(t.x); t.y = to_tf32(t.y); t.z = to_tf32(t.z); t.w = to_tf32(t.w);
            *(float4*)(As + (srow + 32 * i) * TSTR + scol) = t;
        }
#pragma unroll
        for (int i = 0; i < 4; i++) {
            float4 t = bv[i];
            t.x = to_tf32(t.x); t.y = to_tf32(t.y); t.z = to_tf32(t.z); t.w = to_tf32(t.w);
            *(float4*)(Bs + (srow + 32 * i) * TSTR + scol) = t;
        }
        __syncthreads();

#pragma unroll
        for (int kk = 0; kk < BK; kk += 8) {
            uint32_t af[2][4], bf[8][2];
#pragma unroll
            for (int i = 0; i < 2; i++)
                ldsm_x4(af[i][0], af[i][1], af[i][2], af[i][3], aoff[i] + kk * 4);
#pragma unroll
            for (int jj = 0; jj < 4; jj++)
                ldsm_x4(bf[2 * jj][0], bf[2 * jj][1],
                        bf[2 * jj + 1][0], bf[2 * jj + 1][1], boff[jj] + kk * 4);
#pragma unroll
            for (int i = 0; i < 2; i++)
#pragma unroll
                for (int j = 0; j < 8; j++)
                    mma_tf32(acc[i][j], af[i], bf[j]);
        }
    }

#pragma unroll
    for (int i = 0; i < 2; i++) {
        int row = by + wm + i * 16 + g;
#pragma unroll
        for (int j = 0; j < 8; j++) {
            int col = bx + wn + j * 8 + a * 2;
            float b0 = bias[col], b1 = bias[col + 1];
            *(float2*)(C + (size_t)row * N + col) =
                make_float2(acc[i][j][0] + b0, acc[i][j][1] + b1);
            *(float2*)(C + (size_t)(row + 8) * N + col) =
                make_float2(acc[i][j][2] + b0, acc[i][j][3] + b1);
        }
    }
}

__global__ __launch_bounds__(256) void qkv_gemm_kernel(
    const float* __restrict__ x, const float* __restrict__ bias)
{
    gemm_lds_body(x, g_wt, bias, g_qkv, QKVN, D_);
}

__global__ __launch_bounds__(256) void out_gemm_kernel(
    const float* __restrict__ bias, float* __restrict__ out)
{
    gemm_lds_body(g_ctx, g_wot, bias, out, D_, D_);
}

// ---------------------------------------------------------------------------
// scores kernel: ldmatrix-fed MMA; epilogue staged through smem so the mask
// load and att store are fully coalesced float4 (fragment-pattern global
// accesses eliminated).  e = exp(s - m_half) + half partials to g_part.
// ---------------------------------------------------------------------------
#define SC_STR 68
#define MS_STR 132
#define SCORES_SMEM ((128 * SC_STR * 2) * 4)   // 69632 B; mask stage 128*132*4 fits

__global__ __launch_bounds__(256) void scores_kernel(
    const float* __restrict__ mask, float* __restrict__ att)
{
    extern __shared__ float sms[];
    float* Qs = sms;
    float* Ks = sms + 128 * SC_STR;
    float* Ms = sms;                       // reuses Q/K region after MMA

    const int bh = blockIdx.z;
    const int b  = bh >> 4, h = bh & 15;
    const int qt = blockIdx.y * 128;
    const int kt = blockIdx.x * 128;
    const int tid = threadIdx.x;
    const int lane = tid & 31, w = tid >> 5;
    const int g = lane >> 2, a = lane & 3;
    const int wm = (w & 3) * 32, wn = (w >> 2) * 64;

    const float* qkv_b = g_qkv + (size_t)(b * S_) * QKVN + h * 192;

    {
        int row = tid >> 4;
        int c4  = (tid & 15) * 4;
#pragma unroll
        for (int i = 0; i < 8; i++) {
            float4 t = *(const float4*)(qkv_b + (size_t)(qt + row + 16 * i) * QKVN + c4);
            t.x = to_tf32(t.x * 0.125f); t.y = to_tf32(t.y * 0.125f);
            t.z = to_tf32(t.z * 0.125f); t.w = to_tf32(t.w * 0.125f);
            *(float4*)(Qs + (row + 16 * i) * SC_STR + c4) = t;
        }
#pragma unroll
        for (int i = 0; i < 8; i++) {
            float4 t = *(const float4*)(qkv_b + (size_t)(kt + row + 16 * i) * QKVN + 64 + c4);
            t.x = to_tf32(t.x); t.y = to_tf32(t.y); t.z = to_tf32(t.z); t.w = to_tf32(t.w);
            *(float4*)(Ks + (row + 16 * i) * SC_STR + c4) = t;
        }
    }
    __syncthreads();

    // ldmatrix lane offsets
    const uint32_t qs_base = (uint32_t)__cvta_generic_to_shared(Qs);
    const uint32_t ks_base = (uint32_t)__cvta_generic_to_shared(Ks);
    uint32_t aoff[2], boff[4];
#pragma unroll
    for (int i = 0; i < 2; i++)
        aoff[i] = qs_base +
            ((wm + i * 16 + ((lane >> 3) & 1) * 8 + (lane & 7)) * SC_STR
             + (lane >> 4) * 4) * 4;
#pragma unroll
    for (int jj = 0; jj < 4; jj++)
        boff[jj] = ks_base +
            ((wn + 8 * (2 * jj + (lane >> 4)) + (lane & 7)) * SC_STR
             + ((lane >> 3) & 1) * 4) * 4;

    float acc[2][8][4];
#pragma unroll
    for (int i = 0; i < 2; i++)
#pragma unroll
        for (int j = 0; j < 8; j++)
#pragma unroll
            for (int v = 0; v < 4; v++) acc[i][j][v] = 0.f;

#pragma unroll
    for (int ks = 0; ks < 8; ks++) {
        int k0 = ks * 8;
        uint32_t af[2][4], bf[8][2];
#pragma unroll
        for (int i = 0; i < 2; i++)
            ldsm_x4(af[i][0], af[i][1], af[i][2], af[i][3], aoff[i] + k0 * 4);
#pragma unroll
        for (int jj = 0; jj < 4; jj++)
            ldsm_x4(bf[2 * jj][0], bf[2 * jj][1],
                    bf[2 * jj + 1][0], bf[2 * jj + 1][1], boff[jj] + k0 * 4);
#pragma unroll
        for (int i = 0; i < 2; i++)
#pragma unroll
            for (int j = 0; j < 8; j++)
                mma_tf32(acc[i][j], af[i], bf[j]);
    }
    __syncthreads();   // Q/K smem dead; safe to overwrite with mask stage

    // ---- stage mask tile coalesced into smem ----
    {
        const float* mb = mask + ((size_t)(b * S_) + qt) * S_ + kt;
        int row = tid >> 4;
        int c4  = (tid & 15) * 4;
#pragma unroll
        for (int i = 0; i < 8; i++) {
#pragma unroll
            for (int hf = 0; hf < 2; hf++) {
                int r = row + 16 * i, c = c4 + 64 * hf;
                *(float4*)(Ms + r * MS_STR + c) =
                    *(const float4*)(mb + (size_t)r * S_ + c);
            }
        }
    }
    __syncthreads();

    // ---- epilogue: fragment math vs smem; e scattered back into Ms ----
    const int half = wn >> 6;
#pragma unroll
    for (int i = 0; i < 2; i++) {
        int r0 = wm + i * 16 + g;
        float mx0 = -1e30f, mx1 = -1e30f;
#pragma unroll
        for (int j = 0; j < 8; j++) {
            int col = wn + j * 8 + a * 2;
            float2 m0 = *(const float2*)(Ms + r0 * MS_STR + col);
            float2 m1 = *(const float2*)(Ms + (r0 + 8) * MS_STR + col);
            acc[i][j][0] += m0.x; acc[i][j][1] += m0.y;
            acc[i][j][2] += m1.x; acc[i][j][3] += m1.y;
            mx0 = fmaxf(mx0, fmaxf(acc[i][j][0], acc[i][j][1]));
            mx1 = fmaxf(mx1, fmaxf(acc[i][j][2], acc[i][j][3]));
        }
        mx0 = fmaxf(mx0, __shfl_xor_sync(~0u, mx0, 1));
        mx0 = fmaxf(mx0, __shfl_xor_sync(~0u, mx0, 2));
        mx1 = fmaxf(mx1, __shfl_xor_sync(~0u, mx1, 1));
        mx1 = fmaxf(mx1, __shfl_xor_sync(~0u, mx1, 2));
        float s0 = 0.f, s1 = 0.f;
#pragma unroll
        for (int j = 0; j < 8; j++) {
            int col = wn + j * 8 + a * 2;
            float e00 = __expf(acc[i][j][0] - mx0);
            float e01 = __expf(acc[i][j][1] - mx0);
            float e10 = __expf(acc[i][j][2] - mx1);
            float e11 = __expf(acc[i][j][3] - mx1);
            s0 += e00 + e01;
            s1 += e10 + e11;
            *(float2*)(Ms + r0 * MS_STR + col)       = make_float2(e00, e01);
            *(float2*)(Ms + (r0 + 8) * MS_STR + col) = make_float2(e10, e11);
        }
        s0 += __shfl_xor_sync(~0u, s0, 1); s0 += __shfl_xor_sync(~0u, s0, 2);
        s1 += __shfl_xor_sync(~0u, s1, 1); s1 += __shfl_xor_sync(~0u, s1, 2);
        if (a == 0) {
            g_part[((size_t)bh * S_ + qt + r0)     * 16 + blockIdx.x * 2 + half] =
                make_float2(mx0, s0);
            g_part[((size_t)bh * S_ + qt + r0 + 8) * 16 + blockIdx.x * 2 + half] =
                make_float2(mx1, s1);
        }
    }
    __syncthreads();

    // ---- coalesced att write ----
    {
        float* ab = att + ((size_t)(b * H_ + h) * S_ + qt) * S_ + kt;
        int row = tid >> 4;
        int c4  = (tid & 15) * 4;
#pragma unroll
        for (int i = 0; i < 8; i++) {
#pragma unroll
            for (int hf = 0; hf < 2; hf++) {
                int r = row + 16 * i, c = c4 + 64 * hf;
                *(float4*)(ab + (size_t)r * S_ + c) =
                    *(const float4*)(Ms + r * MS_STR + c);
            }
        }
    }
}

// ---------------------------------------------------------------------------
// ctx kernel (FROZEN from R15): A-frags via ldmatrix; smem scale table.
// ---------------------------------------------------------------------------
#define CT_ASTR 68
#define CT_VSTR 72
#define CT_AT   (128 * CT_ASTR)
#define CT_VT   (64 * CT_VSTR)
#define CTX_SMEM (2 * (CT_AT + CT_VT) * 4)

__global__ __launch_bounds__(256) void ctx_kernel(float* __restrict__ att)
{
    extern __shared__ float smcx[];
    float* As = smcx;
    float* Vs = smcx + 2 * CT_AT;
    __shared__ float sm_scale[16][128];   // [chunk64][row]

    const int bh = blockIdx.y;
    const int b  = bh >> 4, h = bh & 15;
    const int mt = blockIdx.x * 128;
    const int tid = threadIdx.x;
    const int lane = tid & 31, w = tid >> 5;
    const int g = lane >> 2, a = lane & 3;
    const int wm = (w & 3) * 32, wn = (w >> 2) * 32;

    float* abase = att + ((size_t)bh * S_ + mt) * S_;
    const float* vbase = g_qkv + (size_t)(b * S_) * QKVN + h * 192 + 128;

    const int lrow = tid >> 4;
    const int lc4  = (tid & 15) * 4;

    if (tid < 128) {
        const float2* pp = g_part + ((size_t)bh * S_ + mt + tid) * 16;
        float2 t[16];
#pragma unroll
        for (int k = 0; k < 16; k++) t[k] = pp[k];
        float M = t[0].x;
#pragma unroll
        for (int k = 1; k < 16; k++) M = fmaxf(M, t[k].x);
        float es[16];
        float S = 0.f;
#pragma unroll
        for (int k = 0; k < 16; k++) {
            es[k] = __expf(t[k].x - M);
            S += t[k].y * es[k];
        }
        float inv = 1.f / S;
#pragma unroll
        for (int k = 0; k < 16; k++) sm_scale[k][tid] = es[k] * inv;
    }
    __syncthreads();

    const uint32_t as_base = (uint32_t)__cvta_generic_to_shared(As);
    uint32_t arel[2];
#pragma unroll
    for (int i = 0; i < 2; i++)
        arel[i] = ((wm + i * 16 + ((lane >> 3) & 1) * 8 + (lane & 7)) * CT_ASTR
                   + (lane >> 4) * 4) * 4;

    float4 avr[8], bvr[4];

#define A_LDG(c)                                                               \
    {                                                                          \
        _Pragma("unroll")                                                      \
        for (int i = 0; i < 8; i++)                                            \
            avr[i] = *(const float4*)(abase + (size_t)(lrow + 16 * i) * S_ +   \
                                      (c) * 64 + lc4);                         \
    }
#define A_STS(buf, c)                                                          \
    {                                                                          \
        float* dst = As + (buf) * CT_AT;                                       \
        _Pragma("unroll")                                                      \
        for (int i = 0; i < 8; i++) {                                          \
            float sc_i = sm_scale[c][lrow + 16 * i];                           \
            float4 t = avr[i];                                                 \
            t.x *= sc_i; t.y *= sc_i; t.z *= sc_i; t.w *= sc_i;                \
            *(float4*)(abase + (size_t)(lrow + 16 * i) * S_ + (c) * 64 + lc4) = t; \
            t.x = to_tf32(t.x); t.y = to_tf32(t.y);                            \
            t.z = to_tf32(t.z); t.w = to_tf32(t.w);                            \
            *(float4*)(dst + (lrow + 16 * i) * CT_ASTR + lc4) = t;             \
        }                                                                      \
    }
#define V_LDG(c)                                                               \
    {                                                                          \
        _Pragma("unroll")                                                      \
        for (int i = 0; i < 4; i++)                                            \
            bvr[i] = *(const float4*)(vbase +                                  \
                (size_t)((c) * 64 + lrow + 16 * i) * QKVN + lc4);              \
    }
#define V_STS(buf)                                                             \
    {                                                                          \
        float* dst = Vs + (buf) * CT_VT;                                       \
        _Pragma("unroll")                                                      \
        for (int i = 0; i < 4; i++) {                                          \
            float4 t = bvr[i];                                                 \
            t.x = to_tf32(t.x); t.y = to_tf32(t.y);                            \
            t.z = to_tf32(t.z); t.w = to_tf32(t.w);                            \
            *(float4*)(dst + (lrow + 16 * i) * CT_VSTR + lc4) = t;             \
        }                                                                      \
    }

    float acc[2][4][4];
#pragma unroll
    for (int i = 0; i < 2; i++)
#pragma unroll
        for (int j = 0; j < 4; j++)
#pragma unroll
            for (int v = 0; v < 4; v++) acc[i][j][v] = 0.f;

    const int nk = S_ / 64;
    A_LDG(0); A_STS(0, 0);
    V_LDG(0); V_STS(0);
    A_LDG(1); V_LDG(1);
    __syncthreads();

    for (int c = 0; c < nk; c++) {
        const float* Vb_ = Vs + (c & 1) * CT_VT;
        const uint32_t abuf = as_base + (uint32_t)((c & 1) * CT_AT * 4);
        if (c + 1 < nk) { A_STS((c + 1) & 1, c + 1); V_STS((c + 1) & 1); }
        if (c + 2 < nk) { A_LDG(c + 2); V_LDG(c + 2); }

#pragma unroll
        for (int kk = 0; kk < 64; kk += 8) {
            uint32_t af[2][4], bf[4][2];
#pragma unroll
            for (int i = 0; i < 2; i++)
                ldsm_x4(af[i][0], af[i][1], af[i][2], af[i][3],
                        abuf + arel[i] + kk * 4);
#pragma unroll
            for (int j = 0; j < 4; j++) {
                int n = wn + j * 8 + g;
                bf[j][0] = __float_as_uint(Vb_[(kk + a)     * CT_VSTR + n]);
                bf[j][1] = __float_as_uint(Vb_[(kk + 4 + a) * CT_VSTR + n]);
            }
#pragma unroll
            for (int i = 0; i < 2; i++)
#pragma unroll
                for (int j = 0; j < 4; j++)
                    mma_tf32(acc[i][j], af[i], bf[j]);
        }
        __syncthreads();
    }
#undef A_LDG
#undef A_STS
#undef V_LDG
#undef V_STS

#pragma unroll
    for (int i = 0; i < 2; i++) {
        int row = mt + wm + i * 16 + g;
#pragma unroll
        for (int j = 0; j < 4; j++) {
            int col = wn + j * 8 + a * 2;
            *(float2*)(g_ctx + (size_t)(b * S_ + row) * D_ + h * HD_ + col) =
                make_float2(acc[i][j][0], acc[i][j][1]);
            *(float2*)(g_ctx + (size_t)(b * S_ + row + 8) * D_ + h * HD_ + col) =
                make_float2(acc[i][j][2], acc[i][j][3]);
        }
    }
}

// ---------------------------------------------------------------------------
extern "C" void kernel_launch(void* const* d_in, const int* in_sizes, int n_in,
                              void* d_out, int out_size)
{
    const float* x    = (const float*)d_in[0];
    const float* mask = (const float*)d_in[1];
    const float* Wqkv = (const float*)d_in[2];
    const float* bqkv = (const float*)d_in[3];
    const float* Wo   = (const float*)d_in[4];
    const float* bo   = (const float*)d_in[5];

    float* out = (float*)d_out;                       // [B,S,D]
    float* att = out + (size_t)B_ * S_ * D_;          // [B,H,S,S]

    cudaFuncSetAttribute(scores_kernel,
                         cudaFuncAttributeMaxDynamicSharedMemorySize, SCORES_SMEM);
    cudaFuncSetAttribute(ctx_kernel,
                         cudaFuncAttributeMaxDynamicSharedMemorySize, CTX_SMEM);

    // 0) transpose weights to [n][k]
    {
        dim3 g1(QKVN / 32, D_ / 32);
        transpose_kernel<<<g1, 256>>>(Wqkv, QKVN, D_, 0);
        dim3 g2(D_ / 32, D_ / 32);
        transpose_kernel<<<g2, 256>>>(Wo, D_, D_, 1);
    }
    // 1) fused QKV projection (ldmatrix-fed tf32 GEMM)
    {
        dim3 grid(QKVN / 128, M_ / 128);
        qkv_gemm_kernel<<<grid, 256>>>(x, bqkv);
    }
    // 2a) e-scores + half partials, smem-staged coalesced mask/att I/O
    {
        dim3 grid(S_ / 128, S_ / 128, B_ * H_);
        scores_kernel<<<grid, 256, SCORES_SMEM>>>(mask, att);
    }
    // 2b) ctx = softmax(att) @ V, A-frags via ldmatrix
    {
        dim3 grid(S_ / 128, B_ * H_);
        ctx_kernel<<<grid, 256, CTX_SMEM>>>(att);
    }
    // 3) output projection
    {
        dim3 grid(D_ / 128, M_ / 128);
        out_gemm_kernel<<<grid, 256>>>(bo, out);
    }
}

// round 17
// speedup vs baseline: 1.0693x; 1.0693x over previous
#include <cuda_runtime.h>
#include <cuda_fp16.h>
#include <cstdint>

// Problem constants
#define B_   4
#define S_   1024
#define D_   1024
#define H_   16
#define HD_  64
#define QKVN 3072
#define M_   (B_ * S_)

// Scratch (static device globals — allocation-free per harness rules)
__device__ float g_qkv[(size_t)M_ * QKVN];     // [b,s, h*192 + {q,k,v}*64]
__device__ float g_ctx[(size_t)M_ * D_];       // [b,s, h*64+d]
__device__ float2 g_part[(size_t)B_ * H_ * S_ * 16];  // per (bh,q,chunk64): (max, expsum)
__device__ float g_wt[(size_t)QKVN * D_];      // Wqkv^T : [n][k]
__device__ float g_wot[(size_t)D_ * D_];       // Wo^T   : [n][k]
__device__ __half g_e[(size_t)B_ * H_ * S_ * S_];  // fp16 e-values scratch

// ---------------------------------------------------------------------------
// helpers
// ---------------------------------------------------------------------------
__device__ __forceinline__ float to_tf32(float x) {
    uint32_t u;
    asm("cvt.rna.tf32.f32 %0, %1;" : "=r"(u) : "f"(x));
    return __uint_as_float(u);
}

__device__ __forceinline__ void mma_tf32(float* d, const uint32_t* a, const uint32_t* b) {
    asm volatile(
        "mma.sync.aligned.m16n8k8.row.col.f32.tf32.tf32.f32 "
        "{%0,%1,%2,%3}, {%4,%5,%6,%7}, {%8,%9}, {%0,%1,%2,%3};\n"
        : "+f"(d[0]), "+f"(d[1]), "+f"(d[2]), "+f"(d[3])
        : "r"(a[0]), "r"(a[1]), "r"(a[2]), "r"(a[3]), "r"(b[0]), "r"(b[1]));
}

__device__ __forceinline__ void ldsm_x4(uint32_t& r0, uint32_t& r1,
                                        uint32_t& r2, uint32_t& r3, uint32_t addr) {
    asm volatile("ldmatrix.sync.aligned.m8n8.x4.shared.b16 {%0,%1,%2,%3}, [%4];"
                 : "=r"(r0), "=r"(r1), "=r"(r2), "=r"(r3) : "r"(addr));
}

// ---------------------------------------------------------------------------
// transpose: Wt[n][k] = W[k][n]  (W is [K][N] row-major); dst selected by flag
// ---------------------------------------------------------------------------
__global__ __launch_bounds__(256) void transpose_kernel(
    const float* __restrict__ W, int N, int K, int dst_sel)
{
    float* Wt = dst_sel ? g_wot : g_wt;
    __shared__ float t[32][33];
    const int n0 = blockIdx.x * 32, k0 = blockIdx.y * 32;
    const int tx = threadIdx.x & 31, ty = threadIdx.x >> 5;  // 32 x 8
#pragma unroll
    for (int i = 0; i < 4; i++)
        t[ty + 8 * i][tx] = W[(size_t)(k0 + ty + 8 * i) * N + n0 + tx];
    __syncthreads();
#pragma unroll
    for (int i = 0; i < 4; i++)
        Wt[(size_t)(n0 + ty + 8 * i) * K + k0 + tx] = t[tx][ty + 8 * i];
}

// ---------------------------------------------------------------------------
// tf32 GEMM with ldmatrix fragment feeds (FROZEN from R14).
// ---------------------------------------------------------------------------
#define BK   32
#define TSTR 36

__device__ __forceinline__ void gemm_lds_body(
    const float* __restrict__ A, const float* __restrict__ Bt,
    const float* __restrict__ bias, float* __restrict__ C,
    int N, int K)
{
    __shared__ float As[128 * TSTR];
    __shared__ float Bs[128 * TSTR];

    const int tid  = threadIdx.x;
    const int lane = tid & 31;
    const int wid  = tid >> 5;
    const int wm   = (wid & 3) * 32;
    const int wn   = (wid >> 2) * 64;
    const int bx   = blockIdx.x * 128;
    const int by   = blockIdx.y * 128;

    const int g = lane >> 2;
    const int a = lane & 3;

    float acc[2][8][4];
#pragma unroll
    for (int i = 0; i < 2; i++)
#pragma unroll
        for (int j = 0; j < 8; j++)
#pragma unroll
            for (int v = 0; v < 4; v++) acc[i][j][v] = 0.f;

    const int srow = tid >> 3;
    const int scol = (tid & 7) * 4;

    const uint32_t as_base = (uint32_t)__cvta_generic_to_shared(As);
    const uint32_t bs_base = (uint32_t)__cvta_generic_to_shared(Bs);
    uint32_t aoff[2], boff[4];
#pragma unroll
    for (int i = 0; i < 2; i++)
        aoff[i] = as_base +
            ((wm + i * 16 + ((lane >> 3) & 1) * 8 + (lane & 7)) * TSTR
             + (lane >> 4) * 4) * 4;
#pragma unroll
    for (int jj = 0; jj < 4; jj++)
        boff[jj] = bs_base +
            ((wn + 8 * (2 * jj + (lane >> 4)) + (lane & 7)) * TSTR
             + ((lane >> 3) & 1) * 4) * 4;

    for (int k0 = 0; k0 < K; k0 += BK) {
        float4 av[4], bv[4];
#pragma unroll
        for (int i = 0; i < 4; i++)
            av[i] = *(const float4*)(A + (size_t)(by + srow + 32 * i) * K + k0 + scol);
#pragma unroll
        for (int i = 0; i < 4; i++)
            bv[i] = *(const float4*)(Bt + (size_t)(bx + srow + 32 * i) * K + k0 + scol);

        __syncthreads();
#pragma unroll
        for (int i = 0; i < 4; i++) {
            float4 t = av[i];
            t.x = to_tf32(t.x); t.y = to_tf32(t.y); t.z = to_tf32(t.z); t.w = to_tf32(t.w);
            *(float4*)(As + (srow + 32 * i) * TSTR + scol) = t;
        }
#pragma unroll
        for (int i = 0; i < 4; i++) {
            float4 t = bv[i];
            t.x = to_tf32(t.x); t.y = to_tf32(t.y); t.z = to_tf32(t.z); t.w = to_tf32(t.w);
            *(float4*)(Bs + (srow + 32 * i) * TSTR + scol) = t;
        }
        __syncthreads();

#pragma unroll
        for (int kk = 0; kk < BK; kk += 8) {
            uint32_t af[2][4], bf[8][2];
#pragma unroll
            for (int i = 0; i < 2; i++)
                ldsm_x4(af[i][0], af[i][1], af[i][2], af[i][3], aoff[i] + kk * 4);
#pragma unroll
            for (int jj = 0; jj < 4; jj++)
                ldsm_x4(bf[2 * jj][0], bf[2 * jj][1],
                        bf[2 * jj + 1][0], bf[2 * jj + 1][1], boff[jj] + kk * 4);
#pragma unroll
            for (int i = 0; i < 2; i++)
#pragma unroll
                for (int j = 0; j < 8; j++)
                    mma_tf32(acc[i][j], af[i], bf[j]);
        }
    }

#pragma unroll
    for (int i = 0; i < 2; i++) {
        int row = by + wm + i * 16 + g;
#pragma unroll
        for (int j = 0; j < 8; j++) {
            int col = bx + wn + j * 8 + a * 2;
            float b0 = bias[col], b1 = bias[col + 1];
            *(float2*)(C + (size_t)row * N + col) =
                make_float2(acc[i][j][0] + b0, acc[i][j][1] + b1);
            *(float2*)(C + (size_t)(row + 8) * N + col) =
                make_float2(acc[i][j][2] + b0, acc[i][j][3] + b1);
        }
    }
}

__global__ __launch_bounds__(256) void qkv_gemm_kernel(
    const float* __restrict__ x, const float* __restrict__ bias)
{
    gemm_lds_body(x, g_wt, bias, g_qkv, QKVN, D_);
}

__global__ __launch_bounds__(256) void out_gemm_kernel(
    const float* __restrict__ bias, float* __restrict__ out)
{
    gemm_lds_body(g_ctx, g_wot, bias, out, D_, D_);
}

// ---------------------------------------------------------------------------
// scores kernel (R15 epilogue form): ldmatrix-fed MMA; writes e as fp16 to
// g_e (half the bytes of fp32) + half partials to g_part.
// ---------------------------------------------------------------------------
#define SC_STR 68
#define SCORES_SMEM ((128 * SC_STR * 2) * 4)

__global__ __launch_bounds__(256) void scores_kernel(const float* __restrict__ mask)
{
    extern __shared__ float sms[];
    float* Qs = sms;
    float* Ks = sms + 128 * SC_STR;

    const int bh = blockIdx.z;
    const int b  = bh >> 4, h = bh & 15;
    const int qt = blockIdx.y * 128;
    const int kt = blockIdx.x * 128;
    const int tid = threadIdx.x;
    const int lane = tid & 31, w = tid >> 5;
    const int g = lane >> 2, a = lane & 3;
    const int wm = (w & 3) * 32, wn = (w >> 2) * 64;

    const float* qkv_b = g_qkv + (size_t)(b * S_) * QKVN + h * 192;

    {
        int row = tid >> 4;
        int c4  = (tid & 15) * 4;
#pragma unroll
        for (int i = 0; i < 8; i++) {
            float4 t = *(const float4*)(qkv_b + (size_t)(qt + row + 16 * i) * QKVN + c4);
            t.x = to_tf32(t.x * 0.125f); t.y = to_tf32(t.y * 0.125f);
            t.z = to_tf32(t.z * 0.125f); t.w = to_tf32(t.w * 0.125f);
            *(float4*)(Qs + (row + 16 * i) * SC_STR + c4) = t;
        }
#pragma unroll
        for (int i = 0; i < 8; i++) {
            float4 t = *(const float4*)(qkv_b + (size_t)(kt + row + 16 * i) * QKVN + 64 + c4);
            t.x = to_tf32(t.x); t.y = to_tf32(t.y); t.z = to_tf32(t.z); t.w = to_tf32(t.w);
            *(float4*)(Ks + (row + 16 * i) * SC_STR + c4) = t;
        }
    }
    __syncthreads();

    const uint32_t qs_base = (uint32_t)__cvta_generic_to_shared(Qs);
    const uint32_t ks_base = (uint32_t)__cvta_generic_to_shared(Ks);
    uint32_t aoff[2], boff[4];
#pragma unroll
    for (int i = 0; i < 2; i++)
        aoff[i] = qs_base +
            ((wm + i * 16 + ((lane >> 3) & 1) * 8 + (lane & 7)) * SC_STR
             + (lane >> 4) * 4) * 4;
#pragma unroll
    for (int jj = 0; jj < 4; jj++)
        boff[jj] = ks_base +
            ((wn + 8 * (2 * jj + (lane >> 4)) + (lane & 7)) * SC_STR
             + ((lane >> 3) & 1) * 4) * 4;

    float acc[2][8][4];
#pragma unroll
    for (int i = 0; i < 2; i++)
#pragma unroll
        for (int j = 0; j < 8; j++)
#pragma unroll
            for (int v = 0; v < 4; v++) acc[i][j][v] = 0.f;

#pragma unroll
    for (int ks = 0; ks < 8; ks++) {
        int k0 = ks * 8;
        uint32_t af[2][4], bf[8][2];
#pragma unroll
        for (int i = 0; i < 2; i++)
            ldsm_x4(af[i][0], af[i][1], af[i][2], af[i][3], aoff[i] + k0 * 4);
#pragma unroll
        for (int jj = 0; jj < 4; jj++)
            ldsm_x4(bf[2 * jj][0], bf[2 * jj][1],
                    bf[2 * jj + 1][0], bf[2 * jj + 1][1], boff[jj] + k0 * 4);
#pragma unroll
        for (int i = 0; i < 2; i++)
#pragma unroll
            for (int j = 0; j < 8; j++)
                mma_tf32(acc[i][j], af[i], bf[j]);
    }

    __half* ebase = g_e + ((size_t)bh * S_ + qt) * S_ + kt;
    const float* mbase = mask + ((size_t)(b * S_) + qt) * S_ + kt;
    const int half = wn >> 6;
#pragma unroll
    for (int i = 0; i < 2; i++) {
        int r0 = wm + i * 16 + g;
        float mx0 = -1e30f, mx1 = -1e30f;
#pragma unroll
        for (int j = 0; j < 8; j++) {
            int col = wn + j * 8 + a * 2;
            float2 m0 = *(const float2*)(mbase + (size_t)r0 * S_ + col);
            float2 m1 = *(const float2*)(mbase + (size_t)(r0 + 8) * S_ + col);
            acc[i][j][0] += m0.x; acc[i][j][1] += m0.y;
            acc[i][j][2] += m1.x; acc[i][j][3] += m1.y;
            mx0 = fmaxf(mx0, fmaxf(acc[i][j][0], acc[i][j][1]));
            mx1 = fmaxf(mx1, fmaxf(acc[i][j][2], acc[i][j][3]));
        }
        mx0 = fmaxf(mx0, __shfl_xor_sync(~0u, mx0, 1));
        mx0 = fmaxf(mx0, __shfl_xor_sync(~0u, mx0, 2));
        mx1 = fmaxf(mx1, __shfl_xor_sync(~0u, mx1, 1));
        mx1 = fmaxf(mx1, __shfl_xor_sync(~0u, mx1, 2));
        float s0 = 0.f, s1 = 0.f;
#pragma unroll
        for (int j = 0; j < 8; j++) {
            int col = wn + j * 8 + a * 2;
            float e00 = __expf(acc[i][j][0] - mx0);
            float e01 = __expf(acc[i][j][1] - mx0);
            float e10 = __expf(acc[i][j][2] - mx1);
            float e11 = __expf(acc[i][j][3] - mx1);
            s0 += e00 + e01;
            s1 += e10 + e11;
            *(__half2*)(ebase + (size_t)r0 * S_ + col)       = __floats2half2_rn(e00, e01);
            *(__half2*)(ebase + (size_t)(r0 + 8) * S_ + col) = __floats2half2_rn(e10, e11);
        }
        s0 += __shfl_xor_sync(~0u, s0, 1); s0 += __shfl_xor_sync(~0u, s0, 2);
        s1 += __shfl_xor_sync(~0u, s1, 1); s1 += __shfl_xor_sync(~0u, s1, 2);
        if (a == 0) {
            g_part[((size_t)bh * S_ + qt + r0)     * 16 + blockIdx.x * 2 + half] =
                make_float2(mx0, s0);
            g_part[((size_t)bh * S_ + qt + r0 + 8) * 16 + blockIdx.x * 2 + half] =
                make_float2(mx1, s1);
        }
    }
}

// ---------------------------------------------------------------------------
// ctx kernel: reads fp16 e, rescales via smem scale table, writes the final
// fp32 normalized att, computes g_ctx = P @ V.  A-frags via ldmatrix.
// ---------------------------------------------------------------------------
#define CT_ASTR 68
#define CT_VSTR 72
#define CT_AT   (128 * CT_ASTR)
#define CT_VT   (64 * CT_VSTR)
#define CTX_SMEM (2 * (CT_AT + CT_VT) * 4)

__global__ __launch_bounds__(256) void ctx_kernel(float* __restrict__ att)
{
    extern __shared__ float smcx[];
    float* As = smcx;
    float* Vs = smcx + 2 * CT_AT;
    __shared__ float sm_scale[16][128];   // [chunk64][row]

    const int bh = blockIdx.y;
    const int b  = bh >> 4, h = bh & 15;
    const int mt = blockIdx.x * 128;
    const int tid = threadIdx.x;
    const int lane = tid & 31, w = tid >> 5;
    const int g = lane >> 2, a = lane & 3;
    const int wm = (w & 3) * 32, wn = (w >> 2) * 32;

    float* abase = att + ((size_t)bh * S_ + mt) * S_;
    const __half* ebase = g_e + ((size_t)bh * S_ + mt) * S_;
    const float* vbase = g_qkv + (size_t)(b * S_) * QKVN + h * 192 + 128;

    const int lrow = tid >> 4;
    const int lc4  = (tid & 15) * 4;

    if (tid < 128) {
        const float2* pp = g_part + ((size_t)bh * S_ + mt + tid) * 16;
        float2 t[16];
#pragma unroll
        for (int k = 0; k < 16; k++) t[k] = pp[k];
        float M = t[0].x;
#pragma unroll
        for (int k = 1; k < 16; k++) M = fmaxf(M, t[k].x);
        float es[16];
        float S = 0.f;
#pragma unroll
        for (int k = 0; k < 16; k++) {
            es[k] = __expf(t[k].x - M);
            S += t[k].y * es[k];
        }
        float inv = 1.f / S;
#pragma unroll
        for (int k = 0; k < 16; k++) sm_scale[k][tid] = es[k] * inv;
    }
    __syncthreads();

    const uint32_t as_base = (uint32_t)__cvta_generic_to_shared(As);
    uint32_t arel[2];
#pragma unroll
    for (int i = 0; i < 2; i++)
        arel[i] = ((wm + i * 16 + ((lane >> 3) & 1) * 8 + (lane & 7)) * CT_ASTR
                   + (lane >> 4) * 4) * 4;

    float4 avr[8], bvr[4];

#define A_LDG(c)                                                               \
    {                                                                          \
        _Pragma("unroll")                                                      \
        for (int i = 0; i < 8; i++) {                                          \
            uint2 u = *(const uint2*)(ebase + (size_t)(lrow + 16 * i) * S_ +   \
                                      (c) * 64 + lc4);                         \
            float2 f0 = __half22float2(*(__half2*)&u.x);                       \
            float2 f1 = __half22float2(*(__half2*)&u.y);                       \
            avr[i] = make_float4(f0.x, f0.y, f1.x, f1.y);                      \
        }                                                                      \
    }
#define A_STS(buf, c)                                                          \
    {                                                                          \
        float* dst = As + (buf) * CT_AT;                                       \
        _Pragma("unroll")                                                      \
        for (int i = 0; i < 8; i++) {                                          \
            float sc_i = sm_scale[c][lrow + 16 * i];                           \
            float4 t = avr[i];                                                 \
            t.x *= sc_i; t.y *= sc_i; t.z *= sc_i; t.w *= sc_i;                \
            *(float4*)(abase + (size_t)(lrow + 16 * i) * S_ + (c) * 64 + lc4) = t; \
            t.x = to_tf32(t.x); t.y = to_tf32(t.y);                            \
            t.z = to_tf32(t.z); t.w = to_tf32(t.w);                            \
            *(float4*)(dst + (lrow + 16 * i) * CT_ASTR + lc4) = t;             \
        }                                                                      \
    }
#define V_LDG(c)                                                               \
    {                                                                          \
        _Pragma("unroll")                                                      \
        for (int i = 0; i < 4; i++)                                            \
            bvr[i] = *(const float4*)(vbase +                                  \
                (size_t)((c) * 64 + lrow + 16 * i) * QKVN + lc4);              \
    }
#define V_STS(buf)                                                             \
    {                                                                          \
        float* dst = Vs + (buf) * CT_VT;                                       \
        _Pragma("unroll")                                                      \
        for (int i = 0; i < 4; i++) {                                          \
            float4 t = bvr[i];                                                 \
            t.x = to_tf32(t.x); t.y = to_tf32(t.y);                            \
            t.z = to_tf32(t.z); t.w = to_tf32(t.w);                            \
            *(float4*)(dst + (lrow + 16 * i) * CT_VSTR + lc4) = t;             \
        }                                                                      \
    }

    float acc[2][4][4];
#pragma unroll
    for (int i = 0; i < 2; i++)
#pragma unroll
        for (int j = 0; j < 4; j++)
#pragma unroll
            for (int v = 0; v < 4; v++) acc[i][j][v] = 0.f;

    const int nk = S_ / 64;
    A_LDG(0); A_STS(0, 0);
    V_LDG(0); V_STS(0);
    A_LDG(1); V_LDG(1);
    __syncthreads();

    for (int c = 0; c < nk; c++) {
        const float* Vb_ = Vs + (c & 1) * CT_VT;
        const uint32_t abuf = as_base + (uint32_t)((c & 1) * CT_AT * 4);
        if (c + 1 < nk) { A_STS((c + 1) & 1, c + 1); V_STS((c + 1) & 1); }
        if (c + 2 < nk) { A_LDG(c + 2); V_LDG(c + 2); }

#pragma unroll
        for (int kk = 0; kk < 64; kk += 8) {
            uint32_t af[2][4], bf[4][2];
#pragma unroll
            for (int i = 0; i < 2; i++)
                ldsm_x4(af[i][0], af[i][1], af[i][2], af[i][3],
                        abuf + arel[i] + kk * 4);
#pragma unroll
            for (int j = 0; j < 4; j++) {
                int n = wn + j * 8 + g;
                bf[j][0] = __float_as_uint(Vb_[(kk + a)     * CT_VSTR + n]);
                bf[j][1] = __float_as_uint(Vb_[(kk + 4 + a) * CT_VSTR + n]);
            }
#pragma unroll
            for (int i = 0; i < 2; i++)
#pragma unroll
                for (int j = 0; j < 4; j++)
                    mma_tf32(acc[i][j], af[i], bf[j]);
        }
        __syncthreads();
    }
#undef A_LDG
#undef A_STS
#undef V_LDG
#undef V_STS

#pragma unroll
    for (int i = 0; i < 2; i++) {
        int row = mt + wm + i * 16 + g;
#pragma unroll
        for (int j = 0; j < 4; j++) {
            int col = wn + j * 8 + a * 2;
            *(float2*)(g_ctx + (size_t)(b * S_ + row) * D_ + h * HD_ + col) =
                make_float2(acc[i][j][0], acc[i][j][1]);
            *(float2*)(g_ctx + (size_t)(b * S_ + row + 8) * D_ + h * HD_ + col) =
                make_float2(acc[i][j][2], acc[i][j][3]);
        }
    }
}

// ---------------------------------------------------------------------------
extern "C" void kernel_launch(void* const* d_in, const int* in_sizes, int n_in,
                              void* d_out, int out_size)
{
    const float* x    = (const float*)d_in[0];
    const float* mask = (const float*)d_in[1];
    const float* Wqkv = (const float*)d_in[2];
    const float* bqkv = (const float*)d_in[3];
    const float* Wo   = (const float*)d_in[4];
    const float* bo   = (const float*)d_in[5];

    float* out = (float*)d_out;                       // [B,S,D]
    float* att = out + (size_t)B_ * S_ * D_;          // [B,H,S,S]

    cudaFuncSetAttribute(scores_kernel,
                         cudaFuncAttributeMaxDynamicSharedMemorySize, SCORES_SMEM);
    cudaFuncSetAttribute(ctx_kernel,
                         cudaFuncAttributeMaxDynamicSharedMemorySize, CTX_SMEM);

    // 0) transpose weights to [n][k]
    {
        dim3 g1(QKVN / 32, D_ / 32);
        transpose_kernel<<<g1, 256>>>(Wqkv, QKVN, D_, 0);
        dim3 g2(D_ / 32, D_ / 32);
        transpose_kernel<<<g2, 256>>>(Wo, D_, D_, 1);
    }
    // 1) fused QKV projection (ldmatrix-fed tf32 GEMM)
    {
        dim3 grid(QKVN / 128, M_ / 128);
        qkv_gemm_kernel<<<grid, 256>>>(x, bqkv);
    }
    // 2a) e-scores (fp16) + half partials
    {
        dim3 grid(S_ / 128, S_ / 128, B_ * H_);
        scores_kernel<<<grid, 256, SCORES_SMEM>>>(mask);
    }
    // 2b) ctx = softmax @ V; writes final fp32 normalized att
    {
        dim3 grid(S_ / 128, B_ * H_);
        ctx_kernel<<<grid, 256, CTX_SMEM>>>(att);
    }
    // 3) output projection
    {
        dim3 grid(D_ / 128, M_ / 128);
        out_gemm_kernel<<<grid, 256>>>(bo, out);
    }
}